// round 1
// baseline (speedup 1.0000x reference)
#include <cuda_runtime.h>
#include <math.h>

#define BATCH 2
#define SEQ   2048
#define EMB   1024
#define NH    16
#define HD    64
#define M1    (BATCH*SEQ)   /* 4096 */
#define N1    (3*EMB)       /* 3072 */

// Scratch (allocation-free rule: __device__ globals)
__device__ float g_Q [(size_t)BATCH*NH*SEQ*HD];   // [b,h,s,d]
__device__ float g_KT[(size_t)BATCH*NH*HD*SEQ];   // [b,h,d,s]
__device__ float g_V [(size_t)BATCH*NH*SEQ*HD];   // [b,h,s,d]
__device__ float g_AO[(size_t)BATCH*SEQ*EMB];     // attended, [b,s,e]

// ---------------------------------------------------------------------------
// 128x128x8 fp32 SGEMM, 256 threads, 8x8 per thread.
// MODE 0: C = x @ W_qkv + b_qkv, scattered into g_Q / g_KT / g_V
// MODE 1: C = g_AO @ W_out + b_out, written dense to Cout
// ---------------------------------------------------------------------------
template<int MODE>
__global__ __launch_bounds__(256)
void sgemm_k(const float* __restrict__ A,
             const float* __restrict__ Bm,
             const float* __restrict__ bias,
             float* __restrict__ Cout,
             int M, int N, int K)
{
    __shared__ float As[8][132];   // padded: conflict-free transposed store
    __shared__ float Bs[8][128];

    const float* Ap = (MODE == 1) ? (const float*)g_AO : A;

    const int tid = threadIdx.x;
    const int bm = blockIdx.y * 128;
    const int bn = blockIdx.x * 128;
    const int tx = tid & 15;
    const int ty = tid >> 4;

    float c[8][8];
#pragma unroll
    for (int i = 0; i < 8; i++)
#pragma unroll
        for (int j = 0; j < 8; j++) c[i][j] = 0.f;

    for (int k0 = 0; k0 < K; k0 += 8) {
#pragma unroll
        for (int i = 0; i < 4; i++) {
            int id = tid + i * 256;
            As[id & 7][id >> 3] = Ap[(size_t)(bm + (id >> 3)) * K + k0 + (id & 7)];
        }
#pragma unroll
        for (int i = 0; i < 4; i++) {
            int id = tid + i * 256;
            Bs[id >> 7][id & 127] = Bm[(size_t)(k0 + (id >> 7)) * N + bn + (id & 127)];
        }
        __syncthreads();
#pragma unroll
        for (int k = 0; k < 8; k++) {
            float4 a0 = *(const float4*)&As[k][ty * 8];
            float4 a1 = *(const float4*)&As[k][ty * 8 + 4];
            float4 b0 = *(const float4*)&Bs[k][tx * 8];
            float4 b1 = *(const float4*)&Bs[k][tx * 8 + 4];
            float a[8] = {a0.x, a0.y, a0.z, a0.w, a1.x, a1.y, a1.z, a1.w};
            float b[8] = {b0.x, b0.y, b0.z, b0.w, b1.x, b1.y, b1.z, b1.w};
#pragma unroll
            for (int i = 0; i < 8; i++)
#pragma unroll
                for (int j = 0; j < 8; j++) c[i][j] += a[i] * b[j];
        }
        __syncthreads();
    }

#pragma unroll
    for (int j = 0; j < 8; j++) {
        const int n = bn + tx * 8 + j;
        const float bv = bias[n];
#pragma unroll
        for (int i = 0; i < 8; i++) {
            const int m = bm + ty * 8 + i;
            const float v = c[i][j] + bv;
            if (MODE == 1) {
                Cout[(size_t)m * N + n] = v;
            } else {
                const int b = m >> 11, s = m & (SEQ - 1);
                const int type = n >> 10, e = n & (EMB - 1);
                const int h = e >> 6, d = e & 63;
                const size_t bh = (size_t)(b * NH + h);
                if (type == 0)      g_Q [(bh * SEQ + s) * HD + d] = v;
                else if (type == 1) g_KT[(bh * HD + d) * SEQ + s] = v;
                else                g_V [(bh * SEQ + s) * HD + d] = v;
            }
        }
    }
}

// ---------------------------------------------------------------------------
// Fused causal attention: scores + softmax + P writeback + P@V.
// One CTA handles 8 query rows of one (b,h). 256 threads.
// Dynamic smem: q tile (8x64) + full score rows (8x2048) = 67584 B.
// ---------------------------------------------------------------------------
__global__ __launch_bounds__(256)
void attn_k(float* __restrict__ attw)
{
    const int tid = threadIdx.x;
    const int q0  = blockIdx.x * 8;
    const int bh  = blockIdx.y;          // b*NH + h

    extern __shared__ float sm[];
    float* q_s  = sm;                    // 8*64
    float* rows = sm + 512;              // 8*2048
    __shared__ float inv8[8];

    const float* Qb  = g_Q  + ((size_t)bh * SEQ + q0) * HD;
    const float* KTh = g_KT + (size_t)bh * HD * SEQ;
    const float* Vh  = g_V  + (size_t)bh * SEQ * HD;

    // load Q tile, pre-scaled by 1/sqrt(64)
#pragma unroll
    for (int idx = tid; idx < 512; idx += 256) q_s[idx] = Qb[idx] * 0.125f;
    __syncthreads();

    const int kend_max = q0 + 8;
    const int nch = (kend_max + 255) >> 8;

    // --- scores: rows[qi][k] = (Q[qi] . K[k]) * scale ---
    for (int kc = 0; kc < nch; kc++) {
        const int k = kc * 256 + tid;
        float acc[8] = {0.f, 0.f, 0.f, 0.f, 0.f, 0.f, 0.f, 0.f};
#pragma unroll 16
        for (int d = 0; d < 64; d++) {
            const float kt = KTh[(size_t)d * SEQ + k];
#pragma unroll
            for (int qi = 0; qi < 8; qi++) acc[qi] += q_s[qi * 64 + d] * kt;
        }
#pragma unroll
        for (int qi = 0; qi < 8; qi++) rows[qi * SEQ + k] = acc[qi];
    }
    __syncthreads();

    // --- softmax: one warp per row (un-normalized exp + inverse sum) ---
    {
        const int qi = tid >> 5, lane = tid & 31;
        const int kend = q0 + qi + 1;
        float* r = rows + qi * SEQ;
        float m = -3.4e38f;
        for (int k = lane; k < kend; k += 32) m = fmaxf(m, r[k]);
#pragma unroll
        for (int o = 16; o; o >>= 1) m = fmaxf(m, __shfl_xor_sync(0xffffffffu, m, o));
        float s = 0.f;
        for (int k = lane; k < kend; k += 32) {
            const float e = __expf(r[k] - m);
            r[k] = e;
            s += e;
        }
#pragma unroll
        for (int o = 16; o; o >>= 1) s += __shfl_xor_sync(0xffffffffu, s, o);
        if (lane == 0) inv8[qi] = 1.f / s;
    }
    __syncthreads();

    // --- normalize, zero the masked tail, write P (coalesced) ---
    float* Pbase = attw + ((size_t)bh * SEQ + q0) * SEQ;
    for (int idx = tid; idx < 8 * SEQ; idx += 256) {
        const int qi = idx >> 11, k = idx & (SEQ - 1);
        const int kend = q0 + qi + 1;
        const float v = (k < kend) ? rows[idx] * inv8[qi] : 0.f;
        rows[idx] = v;
        Pbase[(size_t)qi * SEQ + k] = v;
    }
    __syncthreads();

    // --- P @ V : thread owns (d, k-segment), 4 segments reduced via smem ---
    const int d = tid & 63, seg = tid >> 6;
    float acc[8] = {0.f, 0.f, 0.f, 0.f, 0.f, 0.f, 0.f, 0.f};
    for (int k = seg; k < kend_max; k += 4) {
        const float vv = Vh[(size_t)k * HD + d];
#pragma unroll
        for (int qi = 0; qi < 8; qi++) acc[qi] += rows[qi * SEQ + k] * vv;
    }
    __syncthreads();
#pragma unroll
    for (int qi = 0; qi < 8; qi++) rows[(seg * 8 + qi) * 64 + d] = acc[qi];
    __syncthreads();
    if (seg == 0) {
        const int b = bh >> 4, h = bh & 15;
#pragma unroll
        for (int qi = 0; qi < 8; qi++) {
            const float v = rows[qi * 64 + d] + rows[(8 + qi) * 64 + d] +
                            rows[(16 + qi) * 64 + d] + rows[(24 + qi) * 64 + d];
            g_AO[((size_t)(b * SEQ + q0 + qi)) * EMB + h * HD + d] = v;
        }
    }
}

// ---------------------------------------------------------------------------
extern "C" void kernel_launch(void* const* d_in, const int* in_sizes, int n_in,
                              void* d_out, int out_size)
{
    const float* x    = (const float*)d_in[0];
    const float* Wqkv = (const float*)d_in[1];
    const float* bqkv = (const float*)d_in[2];
    const float* Wout = (const float*)d_in[3];
    const float* bout = (const float*)d_in[4];

    float* out  = (float*)d_out;                          // (B,S,E)
    float* attw = out + (size_t)BATCH * SEQ * EMB;        // (B,H,S,S)

    const int smem = (512 + 8 * SEQ) * (int)sizeof(float); // 67584
    cudaFuncSetAttribute(attn_k, cudaFuncAttributeMaxDynamicSharedMemorySize, smem);

    // 1) QKV projection -> Q / K^T / V scratch
    dim3 g1(N1 / 128, M1 / 128);
    sgemm_k<0><<<g1, 256>>>(x, Wqkv, bqkv, nullptr, M1, N1, EMB);

    // 2) fused causal attention (+ write attention_weights)
    attn_k<<<dim3(SEQ / 8, BATCH * NH), 256, smem>>>(attw);

    // 3) output projection
    dim3 g2(EMB / 128, M1 / 128);
    sgemm_k<1><<<g2, 256>>>(nullptr, Wout, bout, out, M1, EMB, EMB);
}

// round 2
// speedup vs baseline: 1.1878x; 1.1878x over previous
#include <cuda_runtime.h>
#include <math.h>
#include <stdint.h>

#define BATCH 2
#define SEQ   2048
#define EMB   1024
#define NH    16
#define HD    64
#define M1    (BATCH*SEQ)   /* 4096 */
#define N1    (3*EMB)       /* 3072 */
#define KDIM  1024
#define KT    16            /* k-tile */
#define PA    136           /* smem pitch (floats) */

// Scratch (allocation-free rule: __device__ globals)
__device__ float g_Q [(size_t)BATCH*NH*SEQ*HD];   // [b,h,s,d]
__device__ float g_KT[(size_t)BATCH*NH*HD*SEQ];   // [b,h,d,s]
__device__ float g_V [(size_t)BATCH*NH*SEQ*HD];   // [b,h,s,d]
__device__ float g_AO[(size_t)BATCH*SEQ*EMB];     // attended, [b,s,e]

__device__ __forceinline__ uint32_t f2tf32(float v) {
    uint32_t r;
    asm("cvt.rna.tf32.f32 %0, %1;" : "=r"(r) : "f"(v));
    return r;
}

#define MMA(C, A0, A1, A2, A3, B0, B1)                                        \
    asm volatile(                                                             \
        "mma.sync.aligned.m16n8k8.row.col.f32.tf32.tf32.f32 "                 \
        "{%0,%1,%2,%3}, {%4,%5,%6,%7}, {%8,%9}, {%0,%1,%2,%3};"               \
        : "+f"((C)[0]), "+f"((C)[1]), "+f"((C)[2]), "+f"((C)[3])              \
        : "r"(A0), "r"(A1), "r"(A2), "r"(A3), "r"(B0), "r"(B1))

// ---------------------------------------------------------------------------
// 3xTF32 tensor-core GEMM: 128x128 block tile, KT=16 double-buffered,
// 256 threads = 8 warps (2x4), warp tile 64x32, mma.m16n8k8.
// MODE 0: C = x @ W_qkv + b_qkv, scattered into g_Q / g_KT / g_V
// MODE 1: C = g_AO @ W_out + b_out, dense to Cout
// ---------------------------------------------------------------------------
template<int MODE>
__global__ __launch_bounds__(256, 2)
void gemm_tf32(const float* __restrict__ A,
               const float* __restrict__ Bm,
               const float* __restrict__ bias,
               float* __restrict__ Cout,
               int M, int N, int K)
{
    extern __shared__ uint32_t smu[];
    uint32_t* Ah = smu;                    // [2][KT*PA]
    uint32_t* Al = Ah + 2 * KT * PA;
    uint32_t* Bh = Al + 2 * KT * PA;
    uint32_t* Bl = Bh + 2 * KT * PA;

    const float* Ap = (MODE == 1) ? (const float*)g_AO : A;

    const int tid  = threadIdx.x;
    const int lane = tid & 31;
    const int wid  = tid >> 5;
    const int mw   = (wid >> 2) * 64;      // warp m offset within tile
    const int nw   = (wid & 3) * 32;       // warp n offset within tile
    const int g    = lane >> 2;
    const int tig  = lane & 3;
    const int bm   = blockIdx.y * 128;
    const int bn   = blockIdx.x * 128;

    // staging coords
    const int a_m0 = tid >> 2;             // A row (iter0), +64 for iter1
    const int a_k4 = tid & 3;              // A float4 index along k
    const int b_k0 = tid >> 5;             // B row (iter0), +8 for iter1

    float c[4][4][4];
#pragma unroll
    for (int i = 0; i < 4; i++)
#pragma unroll
        for (int j = 0; j < 4; j++)
#pragma unroll
            for (int l = 0; l < 4; l++) c[i][j][l] = 0.f;

    const int NKT = K / KT;
    float4 ra[2], rb[2];

    // ---- prologue: load tile 0 ----
#pragma unroll
    for (int i = 0; i < 2; i++) {
        ra[i] = *(const float4*)&Ap[(size_t)(bm + a_m0 + i * 64) * K + a_k4 * 4];
        rb[i] = *(const float4*)&Bm[(size_t)(b_k0 + i * 8) * N + bn + lane * 4];
    }
    // split + store to buffer 0
    {
        const int buf = 0;
#pragma unroll
        for (int i = 0; i < 2; i++) {
            const int m = a_m0 + i * 64;
            const float av[4] = {ra[i].x, ra[i].y, ra[i].z, ra[i].w};
#pragma unroll
            for (int j = 0; j < 4; j++) {
                const int k = a_k4 * 4 + j;
                const uint32_t hi = f2tf32(av[j]);
                const uint32_t lo = f2tf32(av[j] - __uint_as_float(hi));
                const int dst = buf * KT * PA + k * PA + (m ^ (k & 7));
                Ah[dst] = hi; Al[dst] = lo;
            }
            const int kk = b_k0 + i * 8;
            const float bv[4] = {rb[i].x, rb[i].y, rb[i].z, rb[i].w};
            uint32_t bhv[4], blv[4];
#pragma unroll
            for (int j = 0; j < 4; j++) {
                bhv[j] = f2tf32(bv[j]);
                blv[j] = f2tf32(bv[j] - __uint_as_float(bhv[j]));
            }
            const int dstb = buf * KT * PA + kk * PA + lane * 4;
            *(uint4*)(Bh + dstb) = make_uint4(bhv[0], bhv[1], bhv[2], bhv[3]);
            *(uint4*)(Bl + dstb) = make_uint4(blv[0], blv[1], blv[2], blv[3]);
        }
    }
    __syncthreads();

    for (int kt = 0; kt < NKT; kt++) {
        // ---- prefetch next tile (global) ----
        if (kt + 1 < NKT) {
            const int ko = (kt + 1) * KT;
#pragma unroll
            for (int i = 0; i < 2; i++) {
                ra[i] = *(const float4*)&Ap[(size_t)(bm + a_m0 + i * 64) * K + ko + a_k4 * 4];
                rb[i] = *(const float4*)&Bm[(size_t)(ko + b_k0 + i * 8) * N + bn + lane * 4];
            }
        }

        // ---- compute on current buffer ----
        const int cur = kt & 1;
        const uint32_t* ah = Ah + cur * KT * PA;
        const uint32_t* al = Al + cur * KT * PA;
        const uint32_t* bh = Bh + cur * KT * PA;
        const uint32_t* bl = Bl + cur * KT * PA;

#pragma unroll
        for (int ks = 0; ks < KT; ks += 8) {
            const int kA0 = ks + tig, kA1 = ks + tig + 4;
            const int x0 = kA0 & 7, x1 = kA1 & 7;
            uint32_t bhf[4][2], blf[4][2];
#pragma unroll
            for (int ni = 0; ni < 4; ni++) {
                const int n = nw + ni * 8 + g;
                bhf[ni][0] = bh[kA0 * PA + n];
                bhf[ni][1] = bh[kA1 * PA + n];
                blf[ni][0] = bl[kA0 * PA + n];
                blf[ni][1] = bl[kA1 * PA + n];
            }
#pragma unroll
            for (int mi = 0; mi < 4; mi++) {
                const int r0 = mw + mi * 16 + g, r1 = r0 + 8;
                const uint32_t ah0 = ah[kA0 * PA + (r0 ^ x0)];
                const uint32_t ah1 = ah[kA0 * PA + (r1 ^ x0)];
                const uint32_t ah2 = ah[kA1 * PA + (r0 ^ x1)];
                const uint32_t ah3 = ah[kA1 * PA + (r1 ^ x1)];
                const uint32_t al0 = al[kA0 * PA + (r0 ^ x0)];
                const uint32_t al1 = al[kA0 * PA + (r1 ^ x0)];
                const uint32_t al2 = al[kA1 * PA + (r0 ^ x1)];
                const uint32_t al3 = al[kA1 * PA + (r1 ^ x1)];
#pragma unroll
                for (int ni = 0; ni < 4; ni++) {
                    MMA(c[mi][ni], ah0, ah1, ah2, ah3, bhf[ni][0], bhf[ni][1]);
                    MMA(c[mi][ni], ah0, ah1, ah2, ah3, blf[ni][0], blf[ni][1]);
                    MMA(c[mi][ni], al0, al1, al2, al3, bhf[ni][0], bhf[ni][1]);
                }
            }
        }

        // ---- split + store next tile to other buffer ----
        if (kt + 1 < NKT) {
            const int buf = (kt + 1) & 1;
#pragma unroll
            for (int i = 0; i < 2; i++) {
                const int m = a_m0 + i * 64;
                const float av[4] = {ra[i].x, ra[i].y, ra[i].z, ra[i].w};
#pragma unroll
                for (int j = 0; j < 4; j++) {
                    const int k = a_k4 * 4 + j;
                    const uint32_t hi = f2tf32(av[j]);
                    const uint32_t lo = f2tf32(av[j] - __uint_as_float(hi));
                    const int dst = buf * KT * PA + k * PA + (m ^ (k & 7));
                    Ah[dst] = hi; Al[dst] = lo;
                }
                const int kk = b_k0 + i * 8;
                const float bv[4] = {rb[i].x, rb[i].y, rb[i].z, rb[i].w};
                uint32_t bhv[4], blv[4];
#pragma unroll
                for (int j = 0; j < 4; j++) {
                    bhv[j] = f2tf32(bv[j]);
                    blv[j] = f2tf32(bv[j] - __uint_as_float(bhv[j]));
                }
                const int dstb = buf * KT * PA + kk * PA + lane * 4;
                *(uint4*)(Bh + dstb) = make_uint4(bhv[0], bhv[1], bhv[2], bhv[3]);
                *(uint4*)(Bl + dstb) = make_uint4(blv[0], blv[1], blv[2], blv[3]);
            }
        }
        __syncthreads();
    }

    // ---- epilogue ----
#pragma unroll
    for (int mi = 0; mi < 4; mi++) {
#pragma unroll
        for (int ni = 0; ni < 4; ni++) {
            const int r0 = bm + mw + mi * 16 + g;
            const int r1 = r0 + 8;
            const int n0 = bn + nw + ni * 8 + tig * 2;
            const float bv0 = bias[n0], bv1 = bias[n0 + 1];
            const float v00 = c[mi][ni][0] + bv0;
            const float v01 = c[mi][ni][1] + bv1;
            const float v10 = c[mi][ni][2] + bv0;
            const float v11 = c[mi][ni][3] + bv1;
            if (MODE == 1) {
                *(float2*)&Cout[(size_t)r0 * N + n0] = make_float2(v00, v01);
                *(float2*)&Cout[(size_t)r1 * N + n0] = make_float2(v10, v11);
            } else {
#pragma unroll
                for (int e2 = 0; e2 < 4; e2++) {
                    const int m = (e2 < 2) ? r0 : r1;
                    const int n = n0 + (e2 & 1);
                    const float v = (e2 == 0) ? v00 : (e2 == 1) ? v01 : (e2 == 2) ? v10 : v11;
                    const int b = m >> 11, s = m & (SEQ - 1);
                    const int type = n >> 10, e = n & (EMB - 1);
                    const int h = e >> 6, d = e & 63;
                    const size_t bh = (size_t)(b * NH + h);
                    if (type == 0)      g_Q [(bh * SEQ + s) * HD + d] = v;
                    else if (type == 1) g_KT[(bh * HD + d) * SEQ + s] = v;
                    else                g_V [(bh * SEQ + s) * HD + d] = v;
                }
            }
        }
    }
}

// ---------------------------------------------------------------------------
// Fused causal attention (unchanged from R1): 8 query rows per CTA.
// ---------------------------------------------------------------------------
__global__ __launch_bounds__(256)
void attn_k(float* __restrict__ attw)
{
    const int tid = threadIdx.x;
    const int q0  = blockIdx.x * 8;
    const int bh  = blockIdx.y;

    extern __shared__ float sm[];
    float* q_s  = sm;                    // 8*64
    float* rows = sm + 512;              // 8*2048
    __shared__ float inv8[8];

    const float* Qb  = g_Q  + ((size_t)bh * SEQ + q0) * HD;
    const float* KTh = g_KT + (size_t)bh * HD * SEQ;
    const float* Vh  = g_V  + (size_t)bh * SEQ * HD;

#pragma unroll
    for (int idx = tid; idx < 512; idx += 256) q_s[idx] = Qb[idx] * 0.125f;
    __syncthreads();

    const int kend_max = q0 + 8;
    const int nch = (kend_max + 255) >> 8;

    for (int kc = 0; kc < nch; kc++) {
        const int k = kc * 256 + tid;
        float acc[8] = {0.f, 0.f, 0.f, 0.f, 0.f, 0.f, 0.f, 0.f};
#pragma unroll 16
        for (int d = 0; d < 64; d++) {
            const float kt = KTh[(size_t)d * SEQ + k];
#pragma unroll
            for (int qi = 0; qi < 8; qi++) acc[qi] += q_s[qi * 64 + d] * kt;
        }
#pragma unroll
        for (int qi = 0; qi < 8; qi++) rows[qi * SEQ + k] = acc[qi];
    }
    __syncthreads();

    {
        const int qi = tid >> 5, lane = tid & 31;
        const int kend = q0 + qi + 1;
        float* r = rows + qi * SEQ;
        float m = -3.4e38f;
        for (int k = lane; k < kend; k += 32) m = fmaxf(m, r[k]);
#pragma unroll
        for (int o = 16; o; o >>= 1) m = fmaxf(m, __shfl_xor_sync(0xffffffffu, m, o));
        float s = 0.f;
        for (int k = lane; k < kend; k += 32) {
            const float e = __expf(r[k] - m);
            r[k] = e;
            s += e;
        }
#pragma unroll
        for (int o = 16; o; o >>= 1) s += __shfl_xor_sync(0xffffffffu, s, o);
        if (lane == 0) inv8[qi] = 1.f / s;
    }
    __syncthreads();

    float* Pbase = attw + ((size_t)bh * SEQ + q0) * SEQ;
    for (int idx = tid; idx < 8 * SEQ; idx += 256) {
        const int qi = idx >> 11, k = idx & (SEQ - 1);
        const int kend = q0 + qi + 1;
        const float v = (k < kend) ? rows[idx] * inv8[qi] : 0.f;
        rows[idx] = v;
        Pbase[(size_t)qi * SEQ + k] = v;
    }
    __syncthreads();

    const int d = tid & 63, seg = tid >> 6;
    float acc[8] = {0.f, 0.f, 0.f, 0.f, 0.f, 0.f, 0.f, 0.f};
    for (int k = seg; k < kend_max; k += 4) {
        const float vv = Vh[(size_t)k * HD + d];
#pragma unroll
        for (int qi = 0; qi < 8; qi++) acc[qi] += rows[qi * SEQ + k] * vv;
    }
    __syncthreads();
#pragma unroll
    for (int qi = 0; qi < 8; qi++) rows[(seg * 8 + qi) * 64 + d] = acc[qi];
    __syncthreads();
    if (seg == 0) {
        const int b = bh >> 4, h = bh & 15;
#pragma unroll
        for (int qi = 0; qi < 8; qi++) {
            const float v = rows[qi * 64 + d] + rows[(8 + qi) * 64 + d] +
                            rows[(16 + qi) * 64 + d] + rows[(24 + qi) * 64 + d];
            g_AO[((size_t)(b * SEQ + q0 + qi)) * EMB + h * HD + d] = v;
        }
    }
}

// ---------------------------------------------------------------------------
extern "C" void kernel_launch(void* const* d_in, const int* in_sizes, int n_in,
                              void* d_out, int out_size)
{
    const float* x    = (const float*)d_in[0];
    const float* Wqkv = (const float*)d_in[1];
    const float* bqkv = (const float*)d_in[2];
    const float* Wout = (const float*)d_in[3];
    const float* bout = (const float*)d_in[4];

    float* out  = (float*)d_out;
    float* attw = out + (size_t)BATCH * SEQ * EMB;

    const int gsmem = 8 * KT * PA * (int)sizeof(uint32_t);   // 69632
    cudaFuncSetAttribute(gemm_tf32<0>, cudaFuncAttributeMaxDynamicSharedMemorySize, gsmem);
    cudaFuncSetAttribute(gemm_tf32<1>, cudaFuncAttributeMaxDynamicSharedMemorySize, gsmem);
    const int asmem = (512 + 8 * SEQ) * (int)sizeof(float);  // 67584
    cudaFuncSetAttribute(attn_k, cudaFuncAttributeMaxDynamicSharedMemorySize, asmem);

    // 1) QKV projection -> Q / K^T / V
    gemm_tf32<0><<<dim3(N1 / 128, M1 / 128), 256, gsmem>>>(x, Wqkv, bqkv, nullptr, M1, N1, KDIM);

    // 2) fused causal attention (+ write attention_weights)
    attn_k<<<dim3(SEQ / 8, BATCH * NH), 256, asmem>>>(attw);

    // 3) output projection
    gemm_tf32<1><<<dim3(EMB / 128, M1 / 128), 256, gsmem>>>(nullptr, Wout, bout, out, M1, EMB, KDIM);
}

// round 3
// speedup vs baseline: 1.4459x; 1.2173x over previous
#include <cuda_runtime.h>
#include <math.h>
#include <stdint.h>

#define BATCH 2
#define SEQ   2048
#define EMB   1024
#define NH    16
#define HD    64
#define M1    (BATCH*SEQ)   /* 4096 */
#define N1    (3*EMB)       /* 3072 */
#define KDIM  1024
#define KT    16            /* gemm k-tile */
#define PA    136           /* gemm smem pitch (floats) */

// Scratch (allocation-free rule: __device__ globals)
__device__ float g_Q [(size_t)BATCH*NH*SEQ*HD];   // [b,h,s,d]
__device__ float g_KT[(size_t)BATCH*NH*HD*SEQ];   // [b,h,d,s]
__device__ float g_V [(size_t)BATCH*NH*SEQ*HD];   // [b,h,s,d]
__device__ float g_AO[(size_t)BATCH*SEQ*EMB];     // attended, [b,s,e]

__device__ __forceinline__ uint32_t f2tf32(float v) {
    uint32_t r;
    asm("cvt.rna.tf32.f32 %0, %1;" : "=r"(r) : "f"(v));
    return r;
}

#define MMA(C, A0, A1, A2, A3, B0, B1)                                        \
    asm volatile(                                                             \
        "mma.sync.aligned.m16n8k8.row.col.f32.tf32.tf32.f32 "                 \
        "{%0,%1,%2,%3}, {%4,%5,%6,%7}, {%8,%9}, {%0,%1,%2,%3};"               \
        : "+f"((C)[0]), "+f"((C)[1]), "+f"((C)[2]), "+f"((C)[3])              \
        : "r"(A0), "r"(A1), "r"(A2), "r"(A3), "r"(B0), "r"(B1))

// ---------------------------------------------------------------------------
// 3xTF32 tensor-core GEMM (unchanged from R2)
// ---------------------------------------------------------------------------
template<int MODE>
__global__ __launch_bounds__(256, 2)
void gemm_tf32(const float* __restrict__ A,
               const float* __restrict__ Bm,
               const float* __restrict__ bias,
               float* __restrict__ Cout,
               int M, int N, int K)
{
    extern __shared__ uint32_t smu[];
    uint32_t* Ah = smu;
    uint32_t* Al = Ah + 2 * KT * PA;
    uint32_t* Bh = Al + 2 * KT * PA;
    uint32_t* Bl = Bh + 2 * KT * PA;

    const float* Ap = (MODE == 1) ? (const float*)g_AO : A;

    const int tid  = threadIdx.x;
    const int lane = tid & 31;
    const int wid  = tid >> 5;
    const int mw   = (wid >> 2) * 64;
    const int nw   = (wid & 3) * 32;
    const int g    = lane >> 2;
    const int tig  = lane & 3;
    const int bm   = blockIdx.y * 128;
    const int bn   = blockIdx.x * 128;

    const int a_m0 = tid >> 2;
    const int a_k4 = tid & 3;
    const int b_k0 = tid >> 5;

    float c[4][4][4];
#pragma unroll
    for (int i = 0; i < 4; i++)
#pragma unroll
        for (int j = 0; j < 4; j++)
#pragma unroll
            for (int l = 0; l < 4; l++) c[i][j][l] = 0.f;

    const int NKT = K / KT;
    float4 ra[2], rb[2];

#pragma unroll
    for (int i = 0; i < 2; i++) {
        ra[i] = *(const float4*)&Ap[(size_t)(bm + a_m0 + i * 64) * K + a_k4 * 4];
        rb[i] = *(const float4*)&Bm[(size_t)(b_k0 + i * 8) * N + bn + lane * 4];
    }
    {
        const int buf = 0;
#pragma unroll
        for (int i = 0; i < 2; i++) {
            const int m = a_m0 + i * 64;
            const float av[4] = {ra[i].x, ra[i].y, ra[i].z, ra[i].w};
#pragma unroll
            for (int j = 0; j < 4; j++) {
                const int k = a_k4 * 4 + j;
                const uint32_t hi = f2tf32(av[j]);
                const uint32_t lo = f2tf32(av[j] - __uint_as_float(hi));
                const int dst = buf * KT * PA + k * PA + (m ^ (k & 7));
                Ah[dst] = hi; Al[dst] = lo;
            }
            const int kk = b_k0 + i * 8;
            const float bv[4] = {rb[i].x, rb[i].y, rb[i].z, rb[i].w};
            uint32_t bhv[4], blv[4];
#pragma unroll
            for (int j = 0; j < 4; j++) {
                bhv[j] = f2tf32(bv[j]);
                blv[j] = f2tf32(bv[j] - __uint_as_float(bhv[j]));
            }
            const int dstb = buf * KT * PA + kk * PA + lane * 4;
            *(uint4*)(Bh + dstb) = make_uint4(bhv[0], bhv[1], bhv[2], bhv[3]);
            *(uint4*)(Bl + dstb) = make_uint4(blv[0], blv[1], blv[2], blv[3]);
        }
    }
    __syncthreads();

    for (int kt = 0; kt < NKT; kt++) {
        if (kt + 1 < NKT) {
            const int ko = (kt + 1) * KT;
#pragma unroll
            for (int i = 0; i < 2; i++) {
                ra[i] = *(const float4*)&Ap[(size_t)(bm + a_m0 + i * 64) * K + ko + a_k4 * 4];
                rb[i] = *(const float4*)&Bm[(size_t)(ko + b_k0 + i * 8) * N + bn + lane * 4];
            }
        }

        const int cur = kt & 1;
        const uint32_t* ah = Ah + cur * KT * PA;
        const uint32_t* al = Al + cur * KT * PA;
        const uint32_t* bh = Bh + cur * KT * PA;
        const uint32_t* bl = Bl + cur * KT * PA;

#pragma unroll
        for (int ks = 0; ks < KT; ks += 8) {
            const int kA0 = ks + tig, kA1 = ks + tig + 4;
            const int x0 = kA0 & 7, x1 = kA1 & 7;
            uint32_t bhf[4][2], blf[4][2];
#pragma unroll
            for (int ni = 0; ni < 4; ni++) {
                const int n = nw + ni * 8 + g;
                bhf[ni][0] = bh[kA0 * PA + n];
                bhf[ni][1] = bh[kA1 * PA + n];
                blf[ni][0] = bl[kA0 * PA + n];
                blf[ni][1] = bl[kA1 * PA + n];
            }
#pragma unroll
            for (int mi = 0; mi < 4; mi++) {
                const int r0 = mw + mi * 16 + g, r1 = r0 + 8;
                const uint32_t ah0 = ah[kA0 * PA + (r0 ^ x0)];
                const uint32_t ah1 = ah[kA0 * PA + (r1 ^ x0)];
                const uint32_t ah2 = ah[kA1 * PA + (r0 ^ x1)];
                const uint32_t ah3 = ah[kA1 * PA + (r1 ^ x1)];
                const uint32_t al0 = al[kA0 * PA + (r0 ^ x0)];
                const uint32_t al1 = al[kA0 * PA + (r1 ^ x0)];
                const uint32_t al2 = al[kA1 * PA + (r0 ^ x1)];
                const uint32_t al3 = al[kA1 * PA + (r1 ^ x1)];
#pragma unroll
                for (int ni = 0; ni < 4; ni++) {
                    MMA(c[mi][ni], ah0, ah1, ah2, ah3, bhf[ni][0], bhf[ni][1]);
                    MMA(c[mi][ni], ah0, ah1, ah2, ah3, blf[ni][0], blf[ni][1]);
                    MMA(c[mi][ni], al0, al1, al2, al3, bhf[ni][0], bhf[ni][1]);
                }
            }
        }

        if (kt + 1 < NKT) {
            const int buf = (kt + 1) & 1;
#pragma unroll
            for (int i = 0; i < 2; i++) {
                const int m = a_m0 + i * 64;
                const float av[4] = {ra[i].x, ra[i].y, ra[i].z, ra[i].w};
#pragma unroll
                for (int j = 0; j < 4; j++) {
                    const int k = a_k4 * 4 + j;
                    const uint32_t hi = f2tf32(av[j]);
                    const uint32_t lo = f2tf32(av[j] - __uint_as_float(hi));
                    const int dst = buf * KT * PA + k * PA + (m ^ (k & 7));
                    Ah[dst] = hi; Al[dst] = lo;
                }
                const int kk = b_k0 + i * 8;
                const float bv[4] = {rb[i].x, rb[i].y, rb[i].z, rb[i].w};
                uint32_t bhv[4], blv[4];
#pragma unroll
                for (int j = 0; j < 4; j++) {
                    bhv[j] = f2tf32(bv[j]);
                    blv[j] = f2tf32(bv[j] - __uint_as_float(bhv[j]));
                }
                const int dstb = buf * KT * PA + kk * PA + lane * 4;
                *(uint4*)(Bh + dstb) = make_uint4(bhv[0], bhv[1], bhv[2], bhv[3]);
                *(uint4*)(Bl + dstb) = make_uint4(blv[0], blv[1], blv[2], blv[3]);
            }
        }
        __syncthreads();
    }

#pragma unroll
    for (int mi = 0; mi < 4; mi++) {
#pragma unroll
        for (int ni = 0; ni < 4; ni++) {
            const int r0 = bm + mw + mi * 16 + g;
            const int r1 = r0 + 8;
            const int n0 = bn + nw + ni * 8 + tig * 2;
            const float bv0 = bias[n0], bv1 = bias[n0 + 1];
            const float v00 = c[mi][ni][0] + bv0;
            const float v01 = c[mi][ni][1] + bv1;
            const float v10 = c[mi][ni][2] + bv0;
            const float v11 = c[mi][ni][3] + bv1;
            if (MODE == 1) {
                *(float2*)&Cout[(size_t)r0 * N + n0] = make_float2(v00, v01);
                *(float2*)&Cout[(size_t)r1 * N + n0] = make_float2(v10, v11);
            } else {
#pragma unroll
                for (int e2 = 0; e2 < 4; e2++) {
                    const int m = (e2 < 2) ? r0 : r1;
                    const int n = n0 + (e2 & 1);
                    const float v = (e2 == 0) ? v00 : (e2 == 1) ? v01 : (e2 == 2) ? v10 : v11;
                    const int b = m >> 11, s = m & (SEQ - 1);
                    const int type = n >> 10, e = n & (EMB - 1);
                    const int h = e >> 6, d = e & 63;
                    const size_t bh = (size_t)(b * NH + h);
                    if (type == 0)      g_Q [(bh * SEQ + s) * HD + d] = v;
                    else if (type == 1) g_KT[(bh * HD + d) * SEQ + s] = v;
                    else                g_V [(bh * SEQ + s) * HD + d] = v;
                }
            }
        }
    }
}

// ---------------------------------------------------------------------------
// Tensor-core causal attention, two-pass flash-style.
// CTA = 128 query rows of one (b,h); 8 warps, warp = 16-row band.
// Pass1: online (m, l) via 3xTF32 QK^T. Pass2: recompute S, P=exp(s-m)/l,
// write P to attw, accumulate O = P@V (1x tf32).
// ---------------------------------------------------------------------------
#define PQ 68
// smem float offsets
#define O_QH 0
#define O_QL 8704
#define O_KH 17408
#define O_KL 21760
#define O_VT 26112
#define O_PM 30464
#define ATTN_SMEM_F 39168

__global__ __launch_bounds__(256)
void attn2(float* __restrict__ attw)
{
    extern __shared__ float smf[];
    uint32_t* smu = (uint32_t*)smf;

    const int tid  = threadIdx.x;
    const int lane = tid & 31;
    const int wid  = tid >> 5;
    const int g    = lane >> 2;
    const int tig  = lane & 3;
    const int band = wid * 16;
    const int q0   = (gridDim.x - 1 - blockIdx.x) * 128;  // heavy tiles first
    const int bh   = blockIdx.y;

    const float* Qg  = g_Q  + ((size_t)bh * SEQ + q0) * HD;
    const float* KTg = g_KT + (size_t)bh * HD * SEQ;
    const float* Vg  = g_V  + (size_t)bh * SEQ * HD;

    // ---- load Q tile (128 x 64), scale by 1/8, split to tf32 hi/lo ----
#pragma unroll
    for (int i = 0; i < 8; i++) {
        const int idx = tid + i * 256;
        const int r = idx >> 4, c4 = idx & 15;
        float4 v = *(const float4*)&Qg[(size_t)r * HD + c4 * 4];
        v.x *= 0.125f; v.y *= 0.125f; v.z *= 0.125f; v.w *= 0.125f;
        uint32_t h0 = f2tf32(v.x), h1 = f2tf32(v.y), h2 = f2tf32(v.z), h3 = f2tf32(v.w);
        uint32_t l0 = f2tf32(v.x - __uint_as_float(h0));
        uint32_t l1 = f2tf32(v.y - __uint_as_float(h1));
        uint32_t l2 = f2tf32(v.z - __uint_as_float(h2));
        uint32_t l3 = f2tf32(v.w - __uint_as_float(h3));
        *(uint4*)&smu[O_QH + r * PQ + c4 * 4] = make_uint4(h0, h1, h2, h3);
        *(uint4*)&smu[O_QL + r * PQ + c4 * 4] = make_uint4(l0, l1, l2, l3);
    }

    const int nch = (q0 >> 6) + 2;
    const int row0 = q0 + band + g;
    const int row1 = row0 + 8;

    float m0 = -1e30f, m1 = -1e30f, l0 = 0.f, l1 = 0.f;

    // =============================== PASS 1 ===============================
    for (int kc = 0; kc < nch; kc++) {
        const int s0 = kc * 64;
        __syncthreads();
        // load K chunk (as [d][key]) and split
#pragma unroll
        for (int i = 0; i < 4; i++) {
            const int idx = tid + i * 256;
            const int d = idx >> 4, c4 = idx & 15;
            float4 v = *(const float4*)&KTg[(size_t)d * SEQ + s0 + c4 * 4];
            uint32_t h0 = f2tf32(v.x), h1 = f2tf32(v.y), h2 = f2tf32(v.z), h3 = f2tf32(v.w);
            uint32_t l0_ = f2tf32(v.x - __uint_as_float(h0));
            uint32_t l1_ = f2tf32(v.y - __uint_as_float(h1));
            uint32_t l2_ = f2tf32(v.z - __uint_as_float(h2));
            uint32_t l3_ = f2tf32(v.w - __uint_as_float(h3));
            *(uint4*)&smu[O_KH + d * PQ + c4 * 4] = make_uint4(h0, h1, h2, h3);
            *(uint4*)&smu[O_KL + d * PQ + c4 * 4] = make_uint4(l0_, l1_, l2_, l3_);
        }
        __syncthreads();

        float sc[8][4];
#pragma unroll
        for (int nf = 0; nf < 8; nf++)
#pragma unroll
            for (int j = 0; j < 4; j++) sc[nf][j] = 0.f;

#pragma unroll
        for (int k8 = 0; k8 < 8; k8++) {
            const int ka = k8 * 8 + tig;
            const uint32_t ah0 = smu[O_QH + (band + g) * PQ + ka];
            const uint32_t ah1 = smu[O_QH + (band + g + 8) * PQ + ka];
            const uint32_t ah2 = smu[O_QH + (band + g) * PQ + ka + 4];
            const uint32_t ah3 = smu[O_QH + (band + g + 8) * PQ + ka + 4];
            const uint32_t al0 = smu[O_QL + (band + g) * PQ + ka];
            const uint32_t al1 = smu[O_QL + (band + g + 8) * PQ + ka];
            const uint32_t al2 = smu[O_QL + (band + g) * PQ + ka + 4];
            const uint32_t al3 = smu[O_QL + (band + g + 8) * PQ + ka + 4];
#pragma unroll
            for (int nf = 0; nf < 8; nf++) {
                const uint32_t kb0 = smu[O_KH + ka * PQ + nf * 8 + g];
                const uint32_t kb1 = smu[O_KH + (ka + 4) * PQ + nf * 8 + g];
                const uint32_t kl0 = smu[O_KL + ka * PQ + nf * 8 + g];
                const uint32_t kl1 = smu[O_KL + (ka + 4) * PQ + nf * 8 + g];
                MMA(sc[nf], ah0, ah1, ah2, ah3, kb0, kb1);
                MMA(sc[nf], ah0, ah1, ah2, ah3, kl0, kl1);
                MMA(sc[nf], al0, al1, al2, al3, kb0, kb1);
            }
        }

        // causal mask + online stats
        float cm0 = -1e30f, cm1 = -1e30f;
#pragma unroll
        for (int nf = 0; nf < 8; nf++) {
            const int c01 = s0 + nf * 8 + 2 * tig;
            if (c01     > row0) sc[nf][0] = -1e30f;
            if (c01 + 1 > row0) sc[nf][1] = -1e30f;
            if (c01     > row1) sc[nf][2] = -1e30f;
            if (c01 + 1 > row1) sc[nf][3] = -1e30f;
            cm0 = fmaxf(cm0, fmaxf(sc[nf][0], sc[nf][1]));
            cm1 = fmaxf(cm1, fmaxf(sc[nf][2], sc[nf][3]));
        }
        cm0 = fmaxf(cm0, __shfl_xor_sync(0xffffffffu, cm0, 1));
        cm0 = fmaxf(cm0, __shfl_xor_sync(0xffffffffu, cm0, 2));
        cm1 = fmaxf(cm1, __shfl_xor_sync(0xffffffffu, cm1, 1));
        cm1 = fmaxf(cm1, __shfl_xor_sync(0xffffffffu, cm1, 2));
        const float mn0 = fmaxf(m0, cm0), mn1 = fmaxf(m1, cm1);
        float s0a = 0.f, s1a = 0.f;
#pragma unroll
        for (int nf = 0; nf < 8; nf++) {
            s0a += __expf(sc[nf][0] - mn0) + __expf(sc[nf][1] - mn0);
            s1a += __expf(sc[nf][2] - mn1) + __expf(sc[nf][3] - mn1);
        }
        s0a += __shfl_xor_sync(0xffffffffu, s0a, 1);
        s0a += __shfl_xor_sync(0xffffffffu, s0a, 2);
        s1a += __shfl_xor_sync(0xffffffffu, s1a, 1);
        s1a += __shfl_xor_sync(0xffffffffu, s1a, 2);
        l0 = l0 * __expf(m0 - mn0) + s0a;
        l1 = l1 * __expf(m1 - mn1) + s1a;
        m0 = mn0; m1 = mn1;
    }

    const float invl0 = 1.f / l0;
    const float invl1 = 1.f / l1;

    // =============================== PASS 2 ===============================
    float co[8][4];
#pragma unroll
    for (int df = 0; df < 8; df++)
#pragma unroll
        for (int j = 0; j < 4; j++) co[df][j] = 0.f;

    float* Prow = attw + ((size_t)bh * SEQ + q0) * SEQ;

    for (int kc = 0; kc < nch; kc++) {
        const int s0 = kc * 64;
        __syncthreads();
        // load K chunk split + V chunk (tf32)
#pragma unroll
        for (int i = 0; i < 4; i++) {
            const int idx = tid + i * 256;
            const int d = idx >> 4, c4 = idx & 15;
            float4 v = *(const float4*)&KTg[(size_t)d * SEQ + s0 + c4 * 4];
            uint32_t h0 = f2tf32(v.x), h1 = f2tf32(v.y), h2 = f2tf32(v.z), h3 = f2tf32(v.w);
            uint32_t l0_ = f2tf32(v.x - __uint_as_float(h0));
            uint32_t l1_ = f2tf32(v.y - __uint_as_float(h1));
            uint32_t l2_ = f2tf32(v.z - __uint_as_float(h2));
            uint32_t l3_ = f2tf32(v.w - __uint_as_float(h3));
            *(uint4*)&smu[O_KH + d * PQ + c4 * 4] = make_uint4(h0, h1, h2, h3);
            *(uint4*)&smu[O_KL + d * PQ + c4 * 4] = make_uint4(l0_, l1_, l2_, l3_);
            float4 vv = *(const float4*)&Vg[(size_t)(s0 + d) * HD + c4 * 4];
            *(uint4*)&smu[O_VT + d * PQ + c4 * 4] =
                make_uint4(f2tf32(vv.x), f2tf32(vv.y), f2tf32(vv.z), f2tf32(vv.w));
        }
        __syncthreads();

        float sc[8][4];
#pragma unroll
        for (int nf = 0; nf < 8; nf++)
#pragma unroll
            for (int j = 0; j < 4; j++) sc[nf][j] = 0.f;

#pragma unroll
        for (int k8 = 0; k8 < 8; k8++) {
            const int ka = k8 * 8 + tig;
            const uint32_t ah0 = smu[O_QH + (band + g) * PQ + ka];
            const uint32_t ah1 = smu[O_QH + (band + g + 8) * PQ + ka];
            const uint32_t ah2 = smu[O_QH + (band + g) * PQ + ka + 4];
            const uint32_t ah3 = smu[O_QH + (band + g + 8) * PQ + ka + 4];
            const uint32_t al0 = smu[O_QL + (band + g) * PQ + ka];
            const uint32_t al1 = smu[O_QL + (band + g + 8) * PQ + ka];
            const uint32_t al2 = smu[O_QL + (band + g) * PQ + ka + 4];
            const uint32_t al3 = smu[O_QL + (band + g + 8) * PQ + ka + 4];
#pragma unroll
            for (int nf = 0; nf < 8; nf++) {
                const uint32_t kb0 = smu[O_KH + ka * PQ + nf * 8 + g];
                const uint32_t kb1 = smu[O_KH + (ka + 4) * PQ + nf * 8 + g];
                const uint32_t kl0 = smu[O_KL + ka * PQ + nf * 8 + g];
                const uint32_t kl1 = smu[O_KL + (ka + 4) * PQ + nf * 8 + g];
                MMA(sc[nf], ah0, ah1, ah2, ah3, kb0, kb1);
                MMA(sc[nf], ah0, ah1, ah2, ah3, kl0, kl1);
                MMA(sc[nf], al0, al1, al2, al3, kb0, kb1);
            }
        }

        // P = exp(s - m) / l  (masked -> 0), store to smem
#pragma unroll
        for (int nf = 0; nf < 8; nf++) {
            const int c01 = s0 + nf * 8 + 2 * tig;
            if (c01     > row0) sc[nf][0] = -1e30f;
            if (c01 + 1 > row0) sc[nf][1] = -1e30f;
            if (c01     > row1) sc[nf][2] = -1e30f;
            if (c01 + 1 > row1) sc[nf][3] = -1e30f;
            const float p0 = __expf(sc[nf][0] - m0) * invl0;
            const float p1 = __expf(sc[nf][1] - m0) * invl0;
            const float p2 = __expf(sc[nf][2] - m1) * invl1;
            const float p3 = __expf(sc[nf][3] - m1) * invl1;
            *(float2*)&smf[O_PM + (band + g) * PQ + nf * 8 + 2 * tig]     = make_float2(p0, p1);
            *(float2*)&smf[O_PM + (band + g + 8) * PQ + nf * 8 + 2 * tig] = make_float2(p2, p3);
        }
        __syncthreads();

        // O += P @ V
#pragma unroll
        for (int k8 = 0; k8 < 8; k8++) {
            const int ka = k8 * 8 + tig;
            const uint32_t a0 = f2tf32(smf[O_PM + (band + g) * PQ + ka]);
            const uint32_t a1 = f2tf32(smf[O_PM + (band + g + 8) * PQ + ka]);
            const uint32_t a2 = f2tf32(smf[O_PM + (band + g) * PQ + ka + 4]);
            const uint32_t a3 = f2tf32(smf[O_PM + (band + g + 8) * PQ + ka + 4]);
#pragma unroll
            for (int df = 0; df < 8; df++) {
                const uint32_t b0 = smu[O_VT + ka * PQ + df * 8 + g];
                const uint32_t b1 = smu[O_VT + (ka + 4) * PQ + df * 8 + g];
                MMA(co[df], a0, a1, a2, a3, b0, b1);
            }
        }

        // write P chunk to gmem (coalesced float4)
#pragma unroll
        for (int i = 0; i < 8; i++) {
            const int idx = tid + i * 256;
            const int r = idx >> 4, c4 = idx & 15;
            *(float4*)&Prow[(size_t)r * SEQ + s0 + c4 * 4] =
                *(float4*)&smf[O_PM + r * PQ + c4 * 4];
        }
    }

    // ---- zero tail of attention_weights ----
    {
        const int ztail = nch * 64;                // == q0 + 128
        const int ncol4 = (SEQ - ztail) >> 2;
        const float4 z = make_float4(0.f, 0.f, 0.f, 0.f);
        for (int idx = tid; idx < 128 * ncol4; idx += 256) {
            const int r = idx / ncol4, c = idx - r * ncol4;
            *(float4*)&Prow[(size_t)r * SEQ + ztail + c * 4] = z;
        }
    }

    // ---- write O ----
    {
        const int b = bh >> 4, h = bh & 15;
#pragma unroll
        for (int df = 0; df < 8; df++) {
            const int d = h * 64 + df * 8 + 2 * tig;
            *(float2*)&g_AO[(size_t)(b * SEQ + row0) * EMB + d] = make_float2(co[df][0], co[df][1]);
            *(float2*)&g_AO[(size_t)(b * SEQ + row1) * EMB + d] = make_float2(co[df][2], co[df][3]);
        }
    }
}

// ---------------------------------------------------------------------------
extern "C" void kernel_launch(void* const* d_in, const int* in_sizes, int n_in,
                              void* d_out, int out_size)
{
    const float* x    = (const float*)d_in[0];
    const float* Wqkv = (const float*)d_in[1];
    const float* bqkv = (const float*)d_in[2];
    const float* Wout = (const float*)d_in[3];
    const float* bout = (const float*)d_in[4];

    float* out  = (float*)d_out;
    float* attw = out + (size_t)BATCH * SEQ * EMB;

    const int gsmem = 8 * KT * PA * (int)sizeof(uint32_t);   // 69632
    cudaFuncSetAttribute(gemm_tf32<0>, cudaFuncAttributeMaxDynamicSharedMemorySize, gsmem);
    cudaFuncSetAttribute(gemm_tf32<1>, cudaFuncAttributeMaxDynamicSharedMemorySize, gsmem);
    const int asmem = ATTN_SMEM_F * (int)sizeof(float);      // 156672
    cudaFuncSetAttribute(attn2, cudaFuncAttributeMaxDynamicSharedMemorySize, asmem);

    gemm_tf32<0><<<dim3(N1 / 128, M1 / 128), 256, gsmem>>>(x, Wqkv, bqkv, nullptr, M1, N1, KDIM);

    attn2<<<dim3(SEQ / 128, BATCH * NH), 256, asmem>>>(attw);

    gemm_tf32<1><<<dim3(EMB / 128, M1 / 128), 256, gsmem>>>(nullptr, Wout, bout, out, M1, EMB, KDIM);
}